// round 16
// baseline (speedup 1.0000x reference)
#include <cuda_runtime.h>
#include <cstdint>

#define NB   2
#define NC   64
#define NH   32
#define NX   64
#define NY   64
#define NZ   64
#define TABD 6
#define F32_EPS 1.1920928955078125e-07f

// Overflow-safe fast tanh: tanh(x) = sign(x) * (1 - t)/(1 + t), t = exp(-2|x|)
__device__ __forceinline__ float fast_tanh(float x) {
    float ax = fabsf(x);
    float t  = __expf(-2.0f * ax);
    float r  = __fdividef(1.0f - t, 1.0f + t);
    return copysignf(r, x);
}

__device__ __forceinline__ float fast_sigmoid(float x) {
    return __fdividef(1.0f, 1.0f + __expf(-x));
}

// Fused kernel: R11 config (best measured: 41.66 us) with ONE change:
// stores use __stwt (write-through, no L2 dirty-line allocation) — the
// logical extremum of the R13->R14 gradient (less write caching = faster).
__global__ void __launch_bounds__(256, 6)
fused_kernel(const float* __restrict__ x,
             const float* __restrict__ tab,
             const float* __restrict__ w1, const float* __restrict__ b1,
             const float* __restrict__ w2, const float* __restrict__ b2,
             const float* __restrict__ wp, const float* __restrict__ bp,
             const float* __restrict__ ws, const float* __restrict__ bs,
             float* __restrict__ out, float* __restrict__ l2_out)
{
    __shared__ __align__(16) float s_w1[192];        // w1 [32][6] flat
    __shared__ float s_w2[32 * 33];                  // w2 padded: row j at j*33
    __shared__ __align__(16) float s_gy[NY];
    __shared__ __align__(16) float s_gz[NZ];
    __shared__ float s_ax[4];                        // (1-scale)*gx for 4 slices
    __shared__ float s_emb [NB][NH];
    __shared__ float s_emb2[NB][NH];
    __shared__ float s_param[8];       // 0:scale 1:shift 2-4:mu_abc 5-7:sigma_abc
    __shared__ float s_sq[640];        // block 0 only

    const int t    = threadIdx.x;      // 0..255
    const int lane = t & 31;
    const int warp = t >> 5;           // 0..7
    const int blk  = blockIdx.x;       // 0..2047
    const int bc   = blk >> 4;         // 0..127
    const int xg   = blk & 15;         // 0..15 (group of 4 x-slices)
    const int b    = bc >> 6;
    const int c    = bc & 63;

    // ---- Stage weights coalesced: w1 (48 float4), w2 (256 float4) ----
    if (t < 48) ((float4*)s_w1)[t] = ((const float4*)w1)[t];
    {
        float4 v = ((const float4*)w2)[t];
        int e0 = t * 4;
        s_w2[((e0    ) >> 5) * 33 + ((e0    ) & 31)] = v.x;
        s_w2[((e0 + 1) >> 5) * 33 + ((e0 + 1) & 31)] = v.y;
        s_w2[((e0 + 2) >> 5) * 33 + ((e0 + 2) & 31)] = v.z;
        s_w2[((e0 + 3) >> 5) * 33 + ((e0 + 3) & 31)] = v.w;
    }
    __syncthreads();

    // ---- MLP layer 1: emb = tanh(tab @ w1.T + b1)  [2,32], from smem ----
    if (t < NB * NH) {
        int bb = t >> 5, j = t & 31;
        float acc = b1[j];
        #pragma unroll
        for (int k = 0; k < TABD; k++) acc += tab[bb * TABD + k] * s_w1[j * TABD + k];
        s_emb[bb][j] = fast_tanh(acc);
    }
    __syncthreads();

    // ---- MLP layer 2: emb2 = tanh(emb @ w2.T + b2)  [2,32], padded smem ----
    if (t < NB * NH) {
        int bb = t >> 5, j = t & 31;
        float acc = b2[j];
        #pragma unroll
        for (int k = 0; k < NH; k++) acc += s_emb[bb][k] * s_w2[j * 33 + k];
        s_emb2[bb][j] = fast_tanh(acc);
    }
    __syncthreads();

    // ---- 8 head params for THIS (b,c): one warp-dot each ----
    {
        float e = s_emb2[b][lane];
        float wgt, bias;
        if (warp < 5) {                // scale, shift, mu_a, mu_b, mu_c
            int row = warp * 64 + c;
            wgt  = wp[row * NH + lane];
            bias = bp[row];
        } else {                       // sigma_a, sigma_b, sigma_c
            int row = (warp - 5) * 64 + c;
            wgt  = ws[row * NH + lane];
            bias = bs[row];
        }
        float acc = e * wgt;
        #pragma unroll
        for (int off = 16; off > 0; off >>= 1)
            acc += __shfl_down_sync(0xffffffffu, acc, off);
        if (lane == 0) {
            acc += bias;
            if (warp >= 2 && warp <= 4) acc = fast_tanh(acc);
            else if (warp >= 5)         acc = fast_sigmoid(acc);
            s_param[warp] = acc;
        }
    }
    __syncthreads();

    // ---- Gaussian tables for this block ----
    if (t < 64) {                      // gy
        float mup = s_param[3] * 32.0f + 31.5f;
        float sgp = s_param[6] * 3.5f + F32_EPS;
        float d = __fdividef((float)t - mup, sgp);
        s_gy[t] = __expf(-0.5f * d * d);
    } else if (t < 128) {              // gz
        int i = t - 64;
        float mup = s_param[4] * 32.0f + 31.5f;
        float sgp = s_param[7] * 3.5f + F32_EPS;
        float d = __fdividef((float)i - mup, sgp);
        s_gz[i] = __expf(-0.5f * d * d);
    } else if (t < 132) {              // ax for the 4 x-slices of this block
        int xi = xg * 4 + (t - 128);
        float mup = s_param[2] * 32.0f + 31.5f;
        float sgp = s_param[5] * 3.5f + F32_EPS;
        float d = __fdividef((float)xi - mup, sgp);
        s_ax[t - 128] = (1.0f - s_param[0]) * __expf(-0.5f * d * d);
    }

    // ---- Block 0 only: scalar l2 over all 128 (b,c) x 5 param groups ----
    if (blockIdx.x == 0) {
        for (int o = t; o < 640; o += 256) {
            int g = o >> 7;            // 0:scale 1:shift 2-4:sigma
            int r = o & 127;
            int bb = r >> 6, cc = r & 63;
            float acc, v;
            if (g < 2) {
                int row = g * 64 + cc;
                acc = bp[row];
                #pragma unroll
                for (int k = 0; k < NH; k++) acc += s_emb2[bb][k] * wp[row * NH + k];
                v = acc;
            } else {
                int row = (g - 2) * 64 + cc;
                acc = bs[row];
                #pragma unroll
                for (int k = 0; k < NH; k++) acc += s_emb2[bb][k] * ws[row * NH + k];
                v = fast_sigmoid(acc);
            }
            s_sq[o] = v * v;
        }
        __syncthreads();
        if (t < 32) {
            float total = 0.0f;
            #pragma unroll
            for (int g = 0; g < 5; g++) {
                float s = s_sq[g * 128 + t] + s_sq[g * 128 + t + 32]
                        + s_sq[g * 128 + t + 64] + s_sq[g * 128 + t + 96];
                #pragma unroll
                for (int off = 16; off > 0; off >>= 1)
                    s += __shfl_down_sync(0xffffffffu, s, off);
                total += sqrtf(s);
            }
            if (t == 0 && l2_out != nullptr) *l2_out = total;
        }
    }
    __syncthreads();   // publishes s_gy / s_gz / s_ax / s_param

    const float sh  = s_param[1];
    const float ax0 = s_ax[0], ax1 = s_ax[1], ax2 = s_ax[2], ax3 = s_ax[3];

    // ---- Streaming loop: 4 independent __ldcs loads in flight; __stwt
    //      write-through stores (no L2 dirty-line allocation). ----
    const size_t base = (size_t)blk * 16384;   // 4 slices * 4096 floats
    const float4* __restrict__ xp = (const float4*)(x   + base);
    float4*       __restrict__ op = (float4*)      (out + base);

    #pragma unroll
    for (int it = 0; it < 4; it++) {
        int idx4 = t + it * 256;               // 0..1023 within a slice
        int y    = idx4 >> 4;
        int z4   = (idx4 & 15) << 2;

        float4 v0 = __ldcs(&xp[idx4]);
        float4 v1 = __ldcs(&xp[idx4 + 1024]);
        float4 v2 = __ldcs(&xp[idx4 + 2048]);
        float4 v3 = __ldcs(&xp[idx4 + 3072]);

        float gyv = s_gy[y];
        float4 gz = *(const float4*)&s_gz[z4];
        float gx_ = gyv * gz.x, gy_ = gyv * gz.y, gz_ = gyv * gz.z, gw_ = gyv * gz.w;

        float4 o;
        o.x = fmaf(v0.x, ax0 * gx_, sh);
        o.y = fmaf(v0.y, ax0 * gy_, sh);
        o.z = fmaf(v0.z, ax0 * gz_, sh);
        o.w = fmaf(v0.w, ax0 * gw_, sh);
        __stwt(&op[idx4], o);

        o.x = fmaf(v1.x, ax1 * gx_, sh);
        o.y = fmaf(v1.y, ax1 * gy_, sh);
        o.z = fmaf(v1.z, ax1 * gz_, sh);
        o.w = fmaf(v1.w, ax1 * gw_, sh);
        __stwt(&op[idx4 + 1024], o);

        o.x = fmaf(v2.x, ax2 * gx_, sh);
        o.y = fmaf(v2.y, ax2 * gy_, sh);
        o.z = fmaf(v2.z, ax2 * gz_, sh);
        o.w = fmaf(v2.w, ax2 * gw_, sh);
        __stwt(&op[idx4 + 2048], o);

        o.x = fmaf(v3.x, ax3 * gx_, sh);
        o.y = fmaf(v3.y, ax3 * gy_, sh);
        o.z = fmaf(v3.z, ax3 * gz_, sh);
        o.w = fmaf(v3.w, ax3 * gw_, sh);
        __stwt(&op[idx4 + 3072], o);
    }
}

extern "C" void kernel_launch(void* const* d_in, const int* in_sizes, int n_in,
                              void* d_out, int out_size)
{
    const float* x   = (const float*)d_in[0];
    const float* tab = (const float*)d_in[1];
    const float* w1  = (const float*)d_in[2];
    const float* b1  = (const float*)d_in[3];
    const float* w2  = (const float*)d_in[4];
    const float* b2  = (const float*)d_in[5];
    const float* wp  = (const float*)d_in[6];
    const float* bp  = (const float*)d_in[7];
    const float* ws  = (const float*)d_in[8];
    const float* bs  = (const float*)d_in[9];

    float* out = (float*)d_out;
    const long long n_vol = (long long)NB * NC * NX * NY * NZ;  // 33,554,432
    float* l2_out = ((long long)out_size > n_vol) ? (out + n_vol) : nullptr;

    fused_kernel<<<2048, 256>>>(x, tab, w1, b1, w2, b2, wp, bp, ws, bs,
                                out, l2_out);
}

// round 17
// speedup vs baseline: 1.0458x; 1.0458x over previous
#include <cuda_runtime.h>
#include <cstdint>

#define NB   2
#define NC   64
#define NH   32
#define NX   64
#define NY   64
#define NZ   64
#define TABD 6
#define F32_EPS 1.1920928955078125e-07f

// Overflow-safe fast tanh: tanh(x) = sign(x) * (1 - t)/(1 + t), t = exp(-2|x|)
__device__ __forceinline__ float fast_tanh(float x) {
    float ax = fabsf(x);
    float t  = __expf(-2.0f * ax);
    float r  = __fdividef(1.0f - t, 1.0f + t);
    return copysignf(r, x);
}

__device__ __forceinline__ float fast_sigmoid(float x) {
    return __fdividef(1.0f, 1.0f + __expf(-x));
}

// sm_100a 256-bit global accesses (LDG.E.256 / STG.E.256), streaming policy.
__device__ __forceinline__ void ldg256_cs(const float* p, float* r) {
    asm volatile("ld.global.cs.v8.f32 {%0,%1,%2,%3,%4,%5,%6,%7}, [%8];"
                 : "=f"(r[0]), "=f"(r[1]), "=f"(r[2]), "=f"(r[3]),
                   "=f"(r[4]), "=f"(r[5]), "=f"(r[6]), "=f"(r[7])
                 : "l"(p));
}
__device__ __forceinline__ void stg256_cs(float* p, const float* r) {
    asm volatile("st.global.cs.v8.f32 [%0], {%1,%2,%3,%4,%5,%6,%7,%8};"
                 :: "l"(p),
                    "f"(r[0]), "f"(r[1]), "f"(r[2]), "f"(r[3]),
                    "f"(r[4]), "f"(r[5]), "f"(r[6]), "f"(r[7])
                 : "memory");
}

// Fused kernel: R11 frame (2048 blocks x 256 thr, 4-slice batch) with the
// streaming loop moved to 256-bit v8 loads/stores — half the LSU/L1tex
// transactions per byte, 1 KB per warp-instruction to the memory controller.
__global__ void __launch_bounds__(256, 4)
fused_kernel(const float* __restrict__ x,
             const float* __restrict__ tab,
             const float* __restrict__ w1, const float* __restrict__ b1,
             const float* __restrict__ w2, const float* __restrict__ b2,
             const float* __restrict__ wp, const float* __restrict__ bp,
             const float* __restrict__ ws, const float* __restrict__ bs,
             float* __restrict__ out, float* __restrict__ l2_out)
{
    __shared__ __align__(16) float s_w1[192];        // w1 [32][6] flat
    __shared__ float s_w2[32 * 33];                  // w2 padded: row j at j*33
    __shared__ __align__(16) float s_gy[NY];
    __shared__ __align__(16) float s_gz[NZ];
    __shared__ float s_ax[4];                        // (1-scale)*gx for 4 slices
    __shared__ float s_emb [NB][NH];
    __shared__ float s_emb2[NB][NH];
    __shared__ float s_param[8];       // 0:scale 1:shift 2-4:mu_abc 5-7:sigma_abc
    __shared__ float s_sq[640];        // block 0 only

    const int t    = threadIdx.x;      // 0..255
    const int lane = t & 31;
    const int warp = t >> 5;           // 0..7
    const int blk  = blockIdx.x;       // 0..2047
    const int bc   = blk >> 4;         // 0..127
    const int xg   = blk & 15;         // 0..15 (group of 4 x-slices)
    const int b    = bc >> 6;
    const int c    = bc & 63;

    // ---- Stage weights coalesced: w1 (48 float4), w2 (256 float4) ----
    if (t < 48) ((float4*)s_w1)[t] = ((const float4*)w1)[t];
    {
        float4 v = ((const float4*)w2)[t];
        int e0 = t * 4;
        s_w2[((e0    ) >> 5) * 33 + ((e0    ) & 31)] = v.x;
        s_w2[((e0 + 1) >> 5) * 33 + ((e0 + 1) & 31)] = v.y;
        s_w2[((e0 + 2) >> 5) * 33 + ((e0 + 2) & 31)] = v.z;
        s_w2[((e0 + 3) >> 5) * 33 + ((e0 + 3) & 31)] = v.w;
    }
    __syncthreads();

    // ---- MLP layer 1: emb = tanh(tab @ w1.T + b1)  [2,32], from smem ----
    if (t < NB * NH) {
        int bb = t >> 5, j = t & 31;
        float acc = b1[j];
        #pragma unroll
        for (int k = 0; k < TABD; k++) acc += tab[bb * TABD + k] * s_w1[j * TABD + k];
        s_emb[bb][j] = fast_tanh(acc);
    }
    __syncthreads();

    // ---- MLP layer 2: emb2 = tanh(emb @ w2.T + b2)  [2,32], padded smem ----
    if (t < NB * NH) {
        int bb = t >> 5, j = t & 31;
        float acc = b2[j];
        #pragma unroll
        for (int k = 0; k < NH; k++) acc += s_emb[bb][k] * s_w2[j * 33 + k];
        s_emb2[bb][j] = fast_tanh(acc);
    }
    __syncthreads();

    // ---- 8 head params for THIS (b,c): one warp-dot each ----
    {
        float e = s_emb2[b][lane];
        float wgt, bias;
        if (warp < 5) {                // scale, shift, mu_a, mu_b, mu_c
            int row = warp * 64 + c;
            wgt  = wp[row * NH + lane];
            bias = bp[row];
        } else {                       // sigma_a, sigma_b, sigma_c
            int row = (warp - 5) * 64 + c;
            wgt  = ws[row * NH + lane];
            bias = bs[row];
        }
        float acc = e * wgt;
        #pragma unroll
        for (int off = 16; off > 0; off >>= 1)
            acc += __shfl_down_sync(0xffffffffu, acc, off);
        if (lane == 0) {
            acc += bias;
            if (warp >= 2 && warp <= 4) acc = fast_tanh(acc);
            else if (warp >= 5)         acc = fast_sigmoid(acc);
            s_param[warp] = acc;
        }
    }
    __syncthreads();

    // ---- Gaussian tables for this block ----
    if (t < 64) {                      // gy
        float mup = s_param[3] * 32.0f + 31.5f;
        float sgp = s_param[6] * 3.5f + F32_EPS;
        float d = __fdividef((float)t - mup, sgp);
        s_gy[t] = __expf(-0.5f * d * d);
    } else if (t < 128) {              // gz
        int i = t - 64;
        float mup = s_param[4] * 32.0f + 31.5f;
        float sgp = s_param[7] * 3.5f + F32_EPS;
        float d = __fdividef((float)i - mup, sgp);
        s_gz[i] = __expf(-0.5f * d * d);
    } else if (t < 132) {              // ax for the 4 x-slices of this block
        int xi = xg * 4 + (t - 128);
        float mup = s_param[2] * 32.0f + 31.5f;
        float sgp = s_param[5] * 3.5f + F32_EPS;
        float d = __fdividef((float)xi - mup, sgp);
        s_ax[t - 128] = (1.0f - s_param[0]) * __expf(-0.5f * d * d);
    }

    // ---- Block 0 only: scalar l2 over all 128 (b,c) x 5 param groups ----
    if (blockIdx.x == 0) {
        for (int o = t; o < 640; o += 256) {
            int g = o >> 7;            // 0:scale 1:shift 2-4:sigma
            int r = o & 127;
            int bb = r >> 6, cc = r & 63;
            float acc, v;
            if (g < 2) {
                int row = g * 64 + cc;
                acc = bp[row];
                #pragma unroll
                for (int k = 0; k < NH; k++) acc += s_emb2[bb][k] * wp[row * NH + k];
                v = acc;
            } else {
                int row = (g - 2) * 64 + cc;
                acc = bs[row];
                #pragma unroll
                for (int k = 0; k < NH; k++) acc += s_emb2[bb][k] * ws[row * NH + k];
                v = fast_sigmoid(acc);
            }
            s_sq[o] = v * v;
        }
        __syncthreads();
        if (t < 32) {
            float total = 0.0f;
            #pragma unroll
            for (int g = 0; g < 5; g++) {
                float s = s_sq[g * 128 + t] + s_sq[g * 128 + t + 32]
                        + s_sq[g * 128 + t + 64] + s_sq[g * 128 + t + 96];
                #pragma unroll
                for (int off = 16; off > 0; off >>= 1)
                    s += __shfl_down_sync(0xffffffffu, s, off);
                total += sqrtf(s);
            }
            if (t == 0 && l2_out != nullptr) *l2_out = total;
        }
    }
    __syncthreads();   // publishes s_gy / s_gz / s_ax / s_param

    const float sh = s_param[1];

    // ---- Streaming loop: 256-bit v8 accesses, 4-slice batch. Each thread
    //      moves 32 B per instruction; one gy/gz lookup serves the batch. ----
    const size_t base = (size_t)blk * 16384;   // 4 slices * 4096 floats
    const float* __restrict__ xp = x   + base;
    float*       __restrict__ op = out + base;

    #pragma unroll
    for (int it = 0; it < 2; it++) {
        int idx8 = t + it * 256;               // 0..511 float8 within a slice
        int y    = idx8 >> 3;                  // 8 float8 per z-row
        int z8   = (idx8 & 7) << 3;
        int e0   = idx8 << 3;                  // float offset within slice

        // 4 independent 256-bit loads (one per slice)
        float v0[8], v1[8], v2[8], v3[8];
        ldg256_cs(xp + e0,         v0);
        ldg256_cs(xp + e0 + 4096,  v1);
        ldg256_cs(xp + e0 + 8192,  v2);
        ldg256_cs(xp + e0 + 12288, v3);

        float gyv = s_gy[y];
        float g8[8];
        #pragma unroll
        for (int k = 0; k < 8; k++) g8[k] = gyv * s_gz[z8 + k];

        float o8[8];
        float a0 = s_ax[0];
        #pragma unroll
        for (int k = 0; k < 8; k++) o8[k] = fmaf(v0[k], a0 * g8[k], sh);
        stg256_cs(op + e0, o8);

        float a1 = s_ax[1];
        #pragma unroll
        for (int k = 0; k < 8; k++) o8[k] = fmaf(v1[k], a1 * g8[k], sh);
        stg256_cs(op + e0 + 4096, o8);

        float a2 = s_ax[2];
        #pragma unroll
        for (int k = 0; k < 8; k++) o8[k] = fmaf(v2[k], a2 * g8[k], sh);
        stg256_cs(op + e0 + 8192, o8);

        float a3 = s_ax[3];
        #pragma unroll
        for (int k = 0; k < 8; k++) o8[k] = fmaf(v3[k], a3 * g8[k], sh);
        stg256_cs(op + e0 + 12288, o8);
    }
}

extern "C" void kernel_launch(void* const* d_in, const int* in_sizes, int n_in,
                              void* d_out, int out_size)
{
    const float* x   = (const float*)d_in[0];
    const float* tab = (const float*)d_in[1];
    const float* w1  = (const float*)d_in[2];
    const float* b1  = (const float*)d_in[3];
    const float* w2  = (const float*)d_in[4];
    const float* b2  = (const float*)d_in[5];
    const float* wp  = (const float*)d_in[6];
    const float* bp  = (const float*)d_in[7];
    const float* ws  = (const float*)d_in[8];
    const float* bs  = (const float*)d_in[9];

    float* out = (float*)d_out;
    const long long n_vol = (long long)NB * NC * NX * NY * NZ;  // 33,554,432
    float* l2_out = ((long long)out_size > n_vol) ? (out + n_vol) : nullptr;

    fused_kernel<<<2048, 256>>>(x, tab, w1, b1, w2, b2, wp, bp, ws, bs,
                                out, l2_out);
}